// round 15
// baseline (speedup 1.0000x reference)
#include <cuda_runtime.h>
#include <cuda_bf16.h>

#define FULL_MASK 0xffffffffu
#define EPW 128          // edges per warp-chunk (4 groups x 32 edges)
#define D   32           // feature dim (fixed by problem shape)

// Scratch (no cudaMalloc allowed). Zero-initialized at module load; trailing
// memset graph nodes restore zeros after every call, so each kernel_launch
// (correctness run + every graph replay) sees zeros. Fully deterministic.
__device__ float4 g_sums4[1 << 20];   // 16 MB: N*8 quads, N <= 131072
__device__ float  g_counts[1 << 17];  // per-segment edge counts

// ---------------------------------------------------------------------------
// 128-bit reduction (fire-and-forget) — sm_90+ vector atomic
// ---------------------------------------------------------------------------
__device__ __forceinline__ void red_add_v4(float4* p, float4 s) {
    asm volatile("red.global.add.v4.f32 [%0], {%1, %2, %3, %4};"
                 :: "l"(p), "f"(s.x), "f"(s.y), "f"(s.z), "f"(s.w)
                 : "memory");
}

// flush: one REDG.128 for the run's raw sum; group leader also counts.
__device__ __forceinline__ void flush_seg(int seg, float4 s, int cnt, int sub) {
    red_add_v4(&g_sums4[seg * 8 + sub], s);
    if (sub == 0) atomicAdd(&g_counts[seg], (float)cnt);
}

// ---------------------------------------------------------------------------
// Kernel 1: gather + sorted-segment raw sum + counts (round-13 engine,
// VERBATIM — fastest measured configuration: 25.4 us).
// ---------------------------------------------------------------------------
__global__ void __launch_bounds__(256)
k_agg(const float* __restrict__ src,
      const int*   __restrict__ gidx,
      const int*   __restrict__ sid,
      int E)
{
    const int lane = threadIdx.x & 31;
    const int sub  = lane & 7;
    const long long warp  = ((long long)blockIdx.x * blockDim.x + threadIdx.x) >> 5;
    const long long start = warp * (long long)EPW;
    if (start >= E) return;

    if (start + EPW <= E) {
        // ---------- fast path: full 128-edge chunk ----------
        int4 gi4 = __ldg((const int4*)(gidx + start) + lane);
        int4 si4 = __ldg((const int4*)(sid  + start) + lane);
        int gi[4] = {gi4.x, gi4.y, gi4.z, gi4.w};
        int si[4] = {si4.x, si4.y, si4.z, si4.w};

        int    cur = -1, cnt = 0;
        float4 sum = make_float4(0.f, 0.f, 0.f, 0.f);

        #pragma unroll
        for (int jo = 0; jo < 32; jo += 8) {
            float4 val[8];
            #pragma unroll
            for (int jj = 0; jj < 8; ++jj) {
                const int j = jo + jj;
                int idx = __shfl_sync(FULL_MASK, gi[j & 3], j >> 2, 8);
                val[jj] = __ldg((const float4*)(src + (long long)idx * D) + sub);
            }
            #pragma unroll
            for (int jj = 0; jj < 8; ++jj) {
                const int j = jo + jj;
                int seg = __shfl_sync(FULL_MASK, si[j & 3], j >> 2, 8);
                if (seg != cur) {
                    if (cnt) flush_seg(cur, sum, cnt, sub);
                    cur = seg; sum = make_float4(0.f, 0.f, 0.f, 0.f); cnt = 0;
                }
                sum.x += val[jj].x; sum.y += val[jj].y;
                sum.z += val[jj].z; sum.w += val[jj].w;
                ++cnt;
            }
        }
        if (cnt) flush_seg(cur, sum, cnt, sub);
    } else {
        // ---------- tail path: partial chunk, per-group scalar loop ----------
        const int group = lane >> 3;
        long long gstart = start + (long long)group * 32;
        long long gend   = min(gstart + 32, (long long)E);

        int    cur = -1, cnt = 0;
        float4 sum = make_float4(0.f, 0.f, 0.f, 0.f);

        for (long long e = gstart; e < gend; ++e) {
            int idx = __ldg(gidx + e);
            int seg = __ldg(sid  + e);
            float4 v = __ldg((const float4*)(src + (long long)idx * D) + sub);
            if (seg != cur) {
                if (cnt) flush_seg(cur, sum, cnt, sub);
                cur = seg; sum = make_float4(0.f, 0.f, 0.f, 0.f); cnt = 0;
            }
            sum.x += v.x; sum.y += v.y; sum.z += v.z; sum.w += v.w;
            ++cnt;
        }
        if (cnt) flush_seg(cur, sum, cnt, sub);
    }
}

// ---------------------------------------------------------------------------
// Kernel 2: out = sums/max(cnt,1). PURE — no scratch restoring (that's done
// by trailing memset nodes at driver speed). One thread per quad: max
// parallelism, the measured-best configuration for this pass shape.
// ---------------------------------------------------------------------------
__global__ void __launch_bounds__(256)
k_fin(float4* __restrict__ out4, int nq)
{
    const int i = blockIdx.x * blockDim.x + threadIdx.x;
    if (i >= nq) return;
    const float4 s = g_sums4[i];
    const float  c = g_counts[i >> 3];       // 8 threads same addr -> broadcast
    const float inv = 1.0f / fmaxf(c, 1.0f);
    out4[i] = make_float4(s.x * inv, s.y * inv, s.z * inv, s.w * inv);
}

// ---------------------------------------------------------------------------
extern "C" void kernel_launch(void* const* d_in, const int* in_sizes, int n_in,
                              void* d_out, int out_size)
{
    const float* src  = (const float*)d_in[0];   // [N, 32] f32
    const int*   gidx = (const int*)  d_in[1];   // [E] i32
    const int*   sid  = (const int*)  d_in[2];   // [E] i32 (sorted)
    float4*      out4 = (float4*)d_out;          // [N, 32] f32

    const int E  = in_sizes[1];
    const int N  = out_size / D;
    const int nq = out_size / 4;

    // 1) gather + raw segment sums + counts into zeroed scratch
    {
        long long warps  = ((long long)E + EPW - 1) / EPW;
        long long tcount = warps * 32;
        int blocks = (int)((tcount + 255) / 256);
        k_agg<<<blocks, 256>>>(src, gidx, sid, E);
    }
    // 2) mean -> out (pure)
    {
        int blocks = (nq + 255) / 256;
        k_fin<<<blocks, 256>>>(out4, nq);
    }
    // 3) restore scratch zeros via driver memset nodes (exact used ranges)
    {
        void* sums_addr = nullptr;
        void* cnts_addr = nullptr;
        cudaGetSymbolAddress(&sums_addr, g_sums4);   // pure lookup, no alloc
        cudaGetSymbolAddress(&cnts_addr, g_counts);
        cudaMemsetAsync(sums_addr, 0, (size_t)nq * sizeof(float4), 0);
        cudaMemsetAsync(cnts_addr, 0, (size_t)N  * sizeof(float),  0);
    }
}

// round 17
// speedup vs baseline: 1.0839x; 1.0839x over previous
#include <cuda_runtime.h>
#include <cuda_bf16.h>

#define FULL_MASK 0xffffffffu
#define EPW 128          // edges per warp-chunk (4 groups x 32 edges)
#define D   32           // feature dim (fixed by problem shape)

// Scratch (no cudaMalloc allowed). Zero-initialized at module load; k_fin
// restores zeros inline after consuming (measured cost ~0.9us — cheaper than
// memset nodes), so every kernel_launch call (correctness run + each graph
// replay) sees zeros. No static guards, fully deterministic.
__device__ float4 g_sums4[1 << 20];   // 16 MB: N*8 quads, N <= 131072
__device__ float  g_counts[1 << 17];  // per-segment edge counts

// ---------------------------------------------------------------------------
// 128-bit reduction (fire-and-forget) — sm_90+ vector atomic
// ---------------------------------------------------------------------------
__device__ __forceinline__ void red_add_v4(float4* p, float4 s) {
    asm volatile("red.global.add.v4.f32 [%0], {%1, %2, %3, %4};"
                 :: "l"(p), "f"(s.x), "f"(s.y), "f"(s.z), "f"(s.w)
                 : "memory");
}

// flush: one REDG.128 for the run's raw sum; group leader also counts.
__device__ __forceinline__ void flush_seg(int seg, float4 s, int cnt, int sub) {
    red_add_v4(&g_sums4[seg * 8 + sub], s);
    if (sub == 0) atomicAdd(&g_counts[seg], (float)cnt);
}

// ---------------------------------------------------------------------------
// Kernel 1: gather + sorted-segment raw sum + counts (round-13 engine,
// VERBATIM — fastest measured configuration: 25.4 us, at the LTS cap).
// Warp = 4 groups of 8 lanes. Group g owns contiguous edges
// [start + g*32, start + g*32 + 32). Lane sub owns feature columns
// [sub*4, sub*4+4) as a float4. Phase 1 issues 8 independent LDG.128 row
// reads (MLP=8/lane); phase 2 run-length accumulates, flushing on segment
// change. Nothing else inside the loops.
// ---------------------------------------------------------------------------
__global__ void __launch_bounds__(256)
k_agg(const float* __restrict__ src,
      const int*   __restrict__ gidx,
      const int*   __restrict__ sid,
      int E)
{
    const int lane = threadIdx.x & 31;
    const int sub  = lane & 7;
    const long long warp  = ((long long)blockIdx.x * blockDim.x + threadIdx.x) >> 5;
    const long long start = warp * (long long)EPW;
    if (start >= E) return;

    if (start + EPW <= E) {
        // ---------- fast path: full 128-edge chunk ----------
        int4 gi4 = __ldg((const int4*)(gidx + start) + lane);
        int4 si4 = __ldg((const int4*)(sid  + start) + lane);
        int gi[4] = {gi4.x, gi4.y, gi4.z, gi4.w};
        int si[4] = {si4.x, si4.y, si4.z, si4.w};

        int    cur = -1, cnt = 0;
        float4 sum = make_float4(0.f, 0.f, 0.f, 0.f);

        #pragma unroll
        for (int jo = 0; jo < 32; jo += 8) {
            float4 val[8];
            #pragma unroll
            for (int jj = 0; jj < 8; ++jj) {
                const int j = jo + jj;
                int idx = __shfl_sync(FULL_MASK, gi[j & 3], j >> 2, 8);
                val[jj] = __ldg((const float4*)(src + (long long)idx * D) + sub);
            }
            #pragma unroll
            for (int jj = 0; jj < 8; ++jj) {
                const int j = jo + jj;
                int seg = __shfl_sync(FULL_MASK, si[j & 3], j >> 2, 8);
                if (seg != cur) {
                    if (cnt) flush_seg(cur, sum, cnt, sub);
                    cur = seg; sum = make_float4(0.f, 0.f, 0.f, 0.f); cnt = 0;
                }
                sum.x += val[jj].x; sum.y += val[jj].y;
                sum.z += val[jj].z; sum.w += val[jj].w;
                ++cnt;
            }
        }
        if (cnt) flush_seg(cur, sum, cnt, sub);
    } else {
        // ---------- tail path: partial chunk, per-group scalar loop ----------
        const int group = lane >> 3;
        long long gstart = start + (long long)group * 32;
        long long gend   = min(gstart + 32, (long long)E);

        int    cur = -1, cnt = 0;
        float4 sum = make_float4(0.f, 0.f, 0.f, 0.f);

        for (long long e = gstart; e < gend; ++e) {
            int idx = __ldg(gidx + e);
            int seg = __ldg(sid  + e);
            float4 v = __ldg((const float4*)(src + (long long)idx * D) + sub);
            if (seg != cur) {
                if (cnt) flush_seg(cur, sum, cnt, sub);
                cur = seg; sum = make_float4(0.f, 0.f, 0.f, 0.f); cnt = 0;
            }
            sum.x += v.x; sum.y += v.y; sum.z += v.z; sum.w += v.w;
            ++cnt;
        }
        if (cnt) flush_seg(cur, sum, cnt, sub);
    }
}

// ---------------------------------------------------------------------------
// Kernel 2: out = sums/max(cnt,1) + inline zero-restore (round-3 shape,
// measured-best epilogue: one thread per quad, max parallelism).
// Out write uses .cs (evict-first streaming) — it is never re-read.
// ---------------------------------------------------------------------------
__global__ void __launch_bounds__(256)
k_fin(float4* __restrict__ out4, int nq)
{
    const int i = blockIdx.x * blockDim.x + threadIdx.x;
    if (i >= nq) return;
    const float4 s = __ldg(&g_sums4[i]);          // L2-hot
    const float  c = __ldg(&g_counts[i >> 3]);    // 8 threads same addr
    const float inv = 1.0f / fmaxf(c, 1.0f);
    const float4 r = make_float4(s.x * inv, s.y * inv, s.z * inv, s.w * inv);
    // streaming store to out (write-only data)
    asm volatile("st.global.cs.v4.f32 [%0], {%1, %2, %3, %4};"
                 :: "l"(out4 + i), "f"(r.x), "f"(r.y), "f"(r.z), "f"(r.w)
                 : "memory");
    // restore scratch invariant for the next call / graph replay
    g_sums4[i] = make_float4(0.f, 0.f, 0.f, 0.f);
    if ((i & 7) == 0) g_counts[i >> 3] = 0.0f;
}

// ---------------------------------------------------------------------------
extern "C" void kernel_launch(void* const* d_in, const int* in_sizes, int n_in,
                              void* d_out, int out_size)
{
    const float* src  = (const float*)d_in[0];   // [N, 32] f32
    const int*   gidx = (const int*)  d_in[1];   // [E] i32
    const int*   sid  = (const int*)  d_in[2];   // [E] i32 (sorted)
    float4*      out4 = (float4*)d_out;          // [N, 32] f32

    const int E  = in_sizes[1];
    const int nq = out_size / 4;

    // 1) gather + raw segment sums + counts into zeroed scratch
    {
        long long warps  = ((long long)E + EPW - 1) / EPW;
        long long tcount = warps * 32;
        int blocks = (int)((tcount + 255) / 256);
        k_agg<<<blocks, 256>>>(src, gidx, sid, E);
    }
    // 2) mean -> out, restore scratch zeros inline
    {
        int blocks = (nq + 255) / 256;
        k_fin<<<blocks, 256>>>(out4, nq);
    }
}